// round 4
// baseline (speedup 1.0000x reference)
#include <cuda_runtime.h>
#include <cstdint>

#define N_NODES 100000
#define N_EDGES 1250000
#define IN_CH   128
#define HID_CH  64
#define CLS_CH  32
#define SCAN_B  1024
#define NB      98        // ceil(N_NODES / SCAN_B)

// ---------------- scratch (device globals; alloc-free rule) ----------------
__device__ __align__(16) float g_h1  [(size_t)N_NODES * HID_CH]; // x @ W1
__device__ __align__(16) float g_act1[(size_t)N_NODES * HID_CH]; // relu(A@h1 + b1)
__device__ __align__(16) float g_m2  [(size_t)N_NODES * CLS_CH]; // act1 @ W2
__device__ int g_deg   [N_NODES];
__device__ int g_incl  [N_NODES];
__device__ int g_off   [N_NODES];
__device__ int g_cursor[N_NODES];
__device__ int g_bsum  [128];
__device__ int g_csr_src[N_EDGES];

// ---------------- packed f32x2 helpers ----------------
__device__ __forceinline__ unsigned long long pack2(float a, float b) {
    unsigned long long r;
    asm("mov.b64 %0, {%1, %2};" : "=l"(r) : "f"(a), "f"(b));
    return r;
}
__device__ __forceinline__ unsigned long long fma2(unsigned long long a,
                                                   unsigned long long b,
                                                   unsigned long long c) {
    unsigned long long d;
    asm("fma.rn.f32x2 %0, %1, %2, %3;" : "=l"(d) : "l"(a), "l"(b), "l"(c));
    return d;
}

// ---------------- CSR build ----------------
__global__ void k_zero_cnt() {
    int i = blockIdx.x * blockDim.x + threadIdx.x;
    if (i < N_NODES) g_deg[i] = 0;
}

__global__ void k_hist(const int* __restrict__ dst) {
    int e = blockIdx.x * blockDim.x + threadIdx.x;
    if (e < N_EDGES) atomicAdd(&g_deg[__ldg(dst + e)], 1);
}

// warp-shuffle block scan (inclusive), 3 barriers
__global__ __launch_bounds__(SCAN_B) void k_scan1() {
    __shared__ int swarp[32];
    int tid = threadIdx.x;
    int lane = tid & 31, wid = tid >> 5;
    int i = blockIdx.x * SCAN_B + tid;
    int v = (i < N_NODES) ? g_deg[i] : 0;
    int x = v;
#pragma unroll
    for (int o = 1; o < 32; o <<= 1) {
        int n = __shfl_up_sync(0xffffffffu, x, o);
        if (lane >= o) x += n;
    }
    if (lane == 31) swarp[wid] = x;
    __syncthreads();
    if (wid == 0) {
        int w = swarp[lane];
#pragma unroll
        for (int o = 1; o < 32; o <<= 1) {
            int n = __shfl_up_sync(0xffffffffu, w, o);
            if (lane >= o) w += n;
        }
        swarp[lane] = w;
    }
    __syncthreads();
    int incl = x + (wid > 0 ? swarp[wid - 1] : 0);
    if (i < N_NODES) g_incl[i] = incl;
    if (tid == SCAN_B - 1) g_bsum[blockIdx.x] = incl;
}

// block-base reduction + final exclusive offsets + cursor zeroing
__global__ __launch_bounds__(SCAN_B) void k_scan23() {
    __shared__ int sred[32];
    __shared__ int s_base;
    int tid = threadIdx.x;
    int v = (tid < blockIdx.x) ? g_bsum[tid] : 0;   // blockIdx.x <= 97 < 128
#pragma unroll
    for (int o = 16; o; o >>= 1) v += __shfl_down_sync(0xffffffffu, v, o);
    if ((tid & 31) == 0) sred[tid >> 5] = v;
    __syncthreads();
    if (tid < 32) {
        int w = sred[tid];
#pragma unroll
        for (int o = 16; o; o >>= 1) w += __shfl_down_sync(0xffffffffu, w, o);
        if (tid == 0) s_base = w;
    }
    __syncthreads();
    int i = blockIdx.x * SCAN_B + tid;
    if (i < N_NODES) {
        g_off[i] = g_incl[i] - g_deg[i] + s_base;
        g_cursor[i] = 0;
    }
}

__global__ void k_fill(const int* __restrict__ src, const int* __restrict__ dst) {
    int e = blockIdx.x * blockDim.x + threadIdx.x;
    if (e >= N_EDGES) return;
    int d = __ldg(dst + e);
    int pos = atomicAdd(&g_cursor[d], 1);
    g_csr_src[g_off[d] + pos] = __ldg(src + e);
}

// ---------------- K1: h1 = x @ W1 (128 -> 64), 2 threads per row ----------------
#define G1_STRIDE 20   // 16 cols + 4 pad floats: conflict-free LDS.128
__global__ __launch_bounds__(512) void k_gemm1(const float* __restrict__ x,
                                               const float* __restrict__ W1) {
    __shared__ float sx[256 * G1_STRIDE];      // 20 KB
    __shared__ ulonglong2 sWc[16][16];         // 4 KB : [k][c4]
    int tid = threadIdx.x;
    int r_loc = tid >> 1;          // 0..255
    int half  = tid & 1;           // out-ch half (0: ch 0-31, 1: ch 32-63)
    int row0 = blockIdx.x * 256;
    int row = row0 + r_loc;

    unsigned long long acc[16];    // 32 out-ch -> 32 regs
#pragma unroll
    for (int i = 0; i < 16; i++) acc[i] = 0ull;

    for (int ch = 0; ch < IN_CH / 16; ch++) {   // 8 chunks of 16 k
        __syncthreads();
        {   // x tile: 256 rows x 16 cols = 1024 float4, 2 per thread, coalesced
            int c4 = tid & 3, r = tid >> 2;     // r 0..127
#pragma unroll
            for (int j = 0; j < 2; j++) {
                int rr = r + j * 128;
                int gr = min(row0 + rr, N_NODES - 1);
                float4 v = __ldg(reinterpret_cast<const float4*>(
                                     x + (size_t)gr * IN_CH + ch * 16) + c4);
                *reinterpret_cast<float4*>(&sx[rr * G1_STRIDE + c4 * 4]) = v;
            }
        }
        if (tid < 256) {   // W chunk: 16 k-rows x 64 ch
            int k = tid >> 4, c4 = tid & 15;
            float4 w = __ldg(reinterpret_cast<const float4*>(
                                 W1 + (size_t)(ch * 16 + k) * HID_CH) + c4);
            *reinterpret_cast<float4*>(&sWc[k][c4]) = w;
        }
        __syncthreads();
#pragma unroll
        for (int k4 = 0; k4 < 4; k4++) {
            float4 xv = *reinterpret_cast<const float4*>(&sx[r_loc * G1_STRIDE + k4 * 4]);
#pragma unroll
            for (int j = 0; j < 4; j++) {
                float xs = (j == 0) ? xv.x : (j == 1) ? xv.y : (j == 2) ? xv.z : xv.w;
                unsigned long long xx = pack2(xs, xs);
                int k = k4 * 4 + j;
#pragma unroll
                for (int c4 = 0; c4 < 8; c4++) {
                    ulonglong2 w = sWc[k][half * 8 + c4];
                    acc[2 * c4 + 0] = fma2(xx, w.x, acc[2 * c4 + 0]);
                    acc[2 * c4 + 1] = fma2(xx, w.y, acc[2 * c4 + 1]);
                }
            }
        }
    }
    if (row < N_NODES) {
        ulonglong2* o = reinterpret_cast<ulonglong2*>(
            g_h1 + (size_t)row * HID_CH + half * 32);
#pragma unroll
        for (int c4 = 0; c4 < 8; c4++) {
            ulonglong2 v; v.x = acc[2 * c4]; v.y = acc[2 * c4 + 1];
            o[c4] = v;
        }
    }
}

// ---------------- agg1: act1 = relu(A @ h1 + b1), warp/node, MLP-8 ----------------
__device__ __forceinline__ float2 ld2(int s, int lane) {
    return __ldg(reinterpret_cast<const float2*>(g_h1) + (size_t)s * 32 + lane);
}
__global__ __launch_bounds__(256) void k_agg1(const float* __restrict__ b1) {
    int t = blockIdx.x * 256 + threadIdx.x;
    int node = t >> 5;
    if (node >= N_NODES) return;
    int lane = t & 31;

    int beg = g_off[node];
    int dg  = g_deg[node];

    float2 a0{0,0}, a1{0,0}, a2{0,0}, a3{0,0}, a4{0,0}, a5{0,0}, a6{0,0}, a7{0,0};
    for (int base = 0; base < dg; base += 32) {
        int rem = dg - base;
        int idx = 0;
        if (lane < rem) idx = __ldg(g_csr_src + beg + base + lane);
#pragma unroll
        for (int k = 0; k < 32; k += 8) {
            if (k >= rem) break;
            int s0 = __shfl_sync(0xffffffffu, idx, k + 0);
            int s1 = __shfl_sync(0xffffffffu, idx, k + 1);
            int s2 = __shfl_sync(0xffffffffu, idx, k + 2);
            int s3 = __shfl_sync(0xffffffffu, idx, k + 3);
            int s4 = __shfl_sync(0xffffffffu, idx, k + 4);
            int s5 = __shfl_sync(0xffffffffu, idx, k + 5);
            int s6 = __shfl_sync(0xffffffffu, idx, k + 6);
            int s7 = __shfl_sync(0xffffffffu, idx, k + 7);
            { float2 v = ld2(s0, lane); a0.x += v.x; a0.y += v.y; }
            if (k + 1 < rem) { float2 v = ld2(s1, lane); a1.x += v.x; a1.y += v.y; }
            if (k + 2 < rem) { float2 v = ld2(s2, lane); a2.x += v.x; a2.y += v.y; }
            if (k + 3 < rem) { float2 v = ld2(s3, lane); a3.x += v.x; a3.y += v.y; }
            if (k + 4 < rem) { float2 v = ld2(s4, lane); a4.x += v.x; a4.y += v.y; }
            if (k + 5 < rem) { float2 v = ld2(s5, lane); a5.x += v.x; a5.y += v.y; }
            if (k + 6 < rem) { float2 v = ld2(s6, lane); a6.x += v.x; a6.y += v.y; }
            if (k + 7 < rem) { float2 v = ld2(s7, lane); a7.x += v.x; a7.y += v.y; }
        }
    }
    float2 acc;
    acc.x = ((a0.x + a1.x) + (a2.x + a3.x)) + ((a4.x + a5.x) + (a6.x + a7.x));
    acc.y = ((a0.y + a1.y) + (a2.y + a3.y)) + ((a4.y + a5.y) + (a6.y + a7.y));
    float2 b = reinterpret_cast<const float2*>(b1)[lane];
    acc.x = fmaxf(acc.x + b.x, 0.f);
    acc.y = fmaxf(acc.y + b.y, 0.f);
    reinterpret_cast<float2*>(g_act1 + (size_t)node * HID_CH)[lane] = acc;
}

// ---------------- K3: m2 = act1 @ W2 (64 -> 32), shared-staged ----------------
__global__ __launch_bounds__(256) void k_gemm2(const float* __restrict__ W2) {
    __shared__ float sx[256 * G1_STRIDE];      // 20 KB
    __shared__ ulonglong2 sWc[16][8];          // 2 KB
    int tid = threadIdx.x;
    int row0 = blockIdx.x * 256;
    int row = row0 + tid;

    unsigned long long acc[16];
#pragma unroll
    for (int i = 0; i < 16; i++) acc[i] = 0ull;

    for (int ch = 0; ch < HID_CH / 16; ch++) {   // 4 chunks of 16 k
        __syncthreads();
        {
            int c4 = tid & 3, r = tid >> 2;
#pragma unroll
            for (int j = 0; j < 4; j++) {
                int rr = r + j * 64;
                int gr = min(row0 + rr, N_NODES - 1);
                float4 v = *reinterpret_cast<const float4*>(
                    g_act1 + (size_t)gr * HID_CH + ch * 16 + c4 * 4);
                *reinterpret_cast<float4*>(&sx[rr * G1_STRIDE + c4 * 4]) = v;
            }
        }
        if (tid < 128) {
            int k = tid >> 3, c4 = tid & 7;
            float4 w = __ldg(reinterpret_cast<const float4*>(
                                 W2 + (size_t)(ch * 16 + k) * CLS_CH) + c4);
            *reinterpret_cast<float4*>(&sWc[k][c4]) = w;
        }
        __syncthreads();
#pragma unroll
        for (int k4 = 0; k4 < 4; k4++) {
            float4 xv = *reinterpret_cast<const float4*>(&sx[tid * G1_STRIDE + k4 * 4]);
#pragma unroll
            for (int j = 0; j < 4; j++) {
                float xs = (j == 0) ? xv.x : (j == 1) ? xv.y : (j == 2) ? xv.z : xv.w;
                unsigned long long xx = pack2(xs, xs);
                int k = k4 * 4 + j;
#pragma unroll
                for (int c4 = 0; c4 < 8; c4++) {
                    ulonglong2 w = sWc[k][c4];
                    acc[2 * c4 + 0] = fma2(xx, w.x, acc[2 * c4 + 0]);
                    acc[2 * c4 + 1] = fma2(xx, w.y, acc[2 * c4 + 1]);
                }
            }
        }
    }
    if (row < N_NODES) {
        ulonglong2* o = reinterpret_cast<ulonglong2*>(g_m2 + (size_t)row * CLS_CH);
#pragma unroll
        for (int c4 = 0; c4 < 8; c4++) {
            ulonglong2 v; v.x = acc[2 * c4]; v.y = acc[2 * c4 + 1];
            o[c4] = v;
        }
    }
}

// ---------------- agg2: out = sigmoid(A @ m2 + b2), warp/node, MLP-8 ----------------
__global__ __launch_bounds__(256) void k_agg2(const float* __restrict__ b2,
                                              float* __restrict__ out) {
    int t = blockIdx.x * 256 + threadIdx.x;
    int node = t >> 5;
    if (node >= N_NODES) return;
    int lane = t & 31;

    int beg = g_off[node];
    int dg  = g_deg[node];

    float a0 = 0.f, a1 = 0.f, a2 = 0.f, a3 = 0.f, a4 = 0.f, a5 = 0.f, a6 = 0.f, a7 = 0.f;
    for (int base = 0; base < dg; base += 32) {
        int rem = dg - base;
        int idx = 0;
        if (lane < rem) idx = __ldg(g_csr_src + beg + base + lane);
#pragma unroll
        for (int k = 0; k < 32; k += 8) {
            if (k >= rem) break;
            int s0 = __shfl_sync(0xffffffffu, idx, k + 0);
            int s1 = __shfl_sync(0xffffffffu, idx, k + 1);
            int s2 = __shfl_sync(0xffffffffu, idx, k + 2);
            int s3 = __shfl_sync(0xffffffffu, idx, k + 3);
            int s4 = __shfl_sync(0xffffffffu, idx, k + 4);
            int s5 = __shfl_sync(0xffffffffu, idx, k + 5);
            int s6 = __shfl_sync(0xffffffffu, idx, k + 6);
            int s7 = __shfl_sync(0xffffffffu, idx, k + 7);
            a0 += __ldg(g_m2 + (size_t)s0 * CLS_CH + lane);
            if (k + 1 < rem) a1 += __ldg(g_m2 + (size_t)s1 * CLS_CH + lane);
            if (k + 2 < rem) a2 += __ldg(g_m2 + (size_t)s2 * CLS_CH + lane);
            if (k + 3 < rem) a3 += __ldg(g_m2 + (size_t)s3 * CLS_CH + lane);
            if (k + 4 < rem) a4 += __ldg(g_m2 + (size_t)s4 * CLS_CH + lane);
            if (k + 5 < rem) a5 += __ldg(g_m2 + (size_t)s5 * CLS_CH + lane);
            if (k + 6 < rem) a6 += __ldg(g_m2 + (size_t)s6 * CLS_CH + lane);
            if (k + 7 < rem) a7 += __ldg(g_m2 + (size_t)s7 * CLS_CH + lane);
        }
    }
    float acc = ((a0 + a1) + (a2 + a3)) + ((a4 + a5) + (a6 + a7));
    float v = acc + __ldg(b2 + lane);
    out[(size_t)node * CLS_CH + lane] = 1.f / (1.f + __expf(-v));
}

extern "C" void kernel_launch(void* const* d_in, const int* in_sizes, int n_in,
                              void* d_out, int out_size) {
    const float* x  = (const float*)d_in[0];
    const int*   ei = (const int*)  d_in[1];
    const float* W1 = (const float*)d_in[2];
    const float* b1 = (const float*)d_in[3];
    const float* W2 = (const float*)d_in[4];
    const float* b2 = (const float*)d_in[5];
    float* out = (float*)d_out;
    const int* src = ei;
    const int* dst = ei + N_EDGES;

    // CSR build
    k_zero_cnt<<<(N_NODES + 255) / 256, 256>>>();
    k_hist<<<(N_EDGES + 255) / 256, 256>>>(dst);
    k_scan1<<<NB, SCAN_B>>>();
    k_scan23<<<NB, SCAN_B>>>();
    k_fill<<<(N_EDGES + 255) / 256, 256>>>(src, dst);

    // layer 1
    k_gemm1<<<(N_NODES + 255) / 256, 512>>>(x, W1);
    k_agg1<<<(N_NODES * 32 + 255) / 256, 256>>>(b1);
    // layer 2
    k_gemm2<<<(N_NODES + 255) / 256, 256>>>(W2);
    k_agg2<<<(N_NODES * 32 + 255) / 256, 256>>>(b2, out);
}

// round 5
// speedup vs baseline: 1.1793x; 1.1793x over previous
#include <cuda_runtime.h>
#include <cstdint>

#define N_NODES 100000
#define N_EDGES 1250000
#define IN_CH   128
#define HID_CH  64
#define CLS_CH  32
#define SCAN_B  1024
#define NB      98        // ceil(N_NODES / SCAN_B)

// ---------------- scratch (device globals; alloc-free rule) ----------------
__device__ __align__(16) float g_h1  [(size_t)N_NODES * HID_CH]; // x @ W1
__device__ __align__(16) float g_m2  [(size_t)N_NODES * CLS_CH]; // relu(A@h1+b1) @ W2
__device__ int g_deg   [N_NODES];
__device__ int g_incl  [N_NODES];
__device__ int g_off   [N_NODES];
__device__ int g_cursor[N_NODES];
__device__ int g_bsum  [128];
__device__ int g_csr_src[N_EDGES];

// ---------------- packed f32x2 helpers ----------------
__device__ __forceinline__ unsigned long long pack2(float a, float b) {
    unsigned long long r;
    asm("mov.b64 %0, {%1, %2};" : "=l"(r) : "f"(a), "f"(b));
    return r;
}
__device__ __forceinline__ unsigned long long fma2(unsigned long long a,
                                                   unsigned long long b,
                                                   unsigned long long c) {
    unsigned long long d;
    asm("fma.rn.f32x2 %0, %1, %2, %3;" : "=l"(d) : "l"(a), "l"(b), "l"(c));
    return d;
}

// ---------------- CSR build (R2-proven versions) ----------------
__global__ void k_zero_cnt() {
    int i = blockIdx.x * blockDim.x + threadIdx.x;
    if (i < N_NODES) { g_deg[i] = 0; g_cursor[i] = 0; }
}

__global__ void k_hist(const int* __restrict__ dst) {
    int e = blockIdx.x * blockDim.x + threadIdx.x;
    if (e < N_EDGES) atomicAdd(&g_deg[__ldg(dst + e)], 1);
}

// warp-shuffle block scan (inclusive)
__global__ __launch_bounds__(SCAN_B) void k_scan1() {
    __shared__ int swarp[32];
    int tid = threadIdx.x;
    int lane = tid & 31, wid = tid >> 5;
    int i = blockIdx.x * SCAN_B + tid;
    int v = (i < N_NODES) ? g_deg[i] : 0;
    int x = v;
#pragma unroll
    for (int o = 1; o < 32; o <<= 1) {
        int n = __shfl_up_sync(0xffffffffu, x, o);
        if (lane >= o) x += n;
    }
    if (lane == 31) swarp[wid] = x;
    __syncthreads();
    if (wid == 0) {
        int w = swarp[lane];
#pragma unroll
        for (int o = 1; o < 32; o <<= 1) {
            int n = __shfl_up_sync(0xffffffffu, w, o);
            if (lane >= o) w += n;
        }
        swarp[lane] = w;
    }
    __syncthreads();
    int incl = x + (wid > 0 ? swarp[wid - 1] : 0);
    if (i < N_NODES) g_incl[i] = incl;
    if (tid == SCAN_B - 1) g_bsum[blockIdx.x] = incl;
}

// block-base reduction + final exclusive offsets
__global__ __launch_bounds__(SCAN_B) void k_scan23() {
    __shared__ int sred[32];
    __shared__ int s_base;
    int tid = threadIdx.x;
    int v = (tid < blockIdx.x) ? g_bsum[tid] : 0;   // blockIdx.x <= 97 < 128
#pragma unroll
    for (int o = 16; o; o >>= 1) v += __shfl_down_sync(0xffffffffu, v, o);
    if ((tid & 31) == 0) sred[tid >> 5] = v;
    __syncthreads();
    if (tid < 32) {
        int w = sred[tid];
#pragma unroll
        for (int o = 16; o; o >>= 1) w += __shfl_down_sync(0xffffffffu, w, o);
        if (tid == 0) s_base = w;
    }
    __syncthreads();
    int i = blockIdx.x * SCAN_B + tid;
    if (i < N_NODES) g_off[i] = g_incl[i] - g_deg[i] + s_base;
}

__global__ void k_fill(const int* __restrict__ src, const int* __restrict__ dst) {
    int e = blockIdx.x * blockDim.x + threadIdx.x;
    if (e >= N_EDGES) return;
    int d = __ldg(dst + e);
    int pos = atomicAdd(&g_cursor[d], 1);
    g_csr_src[g_off[d] + pos] = __ldg(src + e);
}

// ---------------- K1: h1 = x @ W1 (128 -> 64), thread-per-row (R2-proven) ----------------
__global__ __launch_bounds__(256) void k_gemm1(const float* __restrict__ x,
                                               const float* __restrict__ W1) {
    __shared__ ulonglong2 sW[IN_CH][HID_CH / 4];   // 32 KB
    for (int i = threadIdx.x; i < IN_CH * HID_CH / 4; i += 256)
        reinterpret_cast<ulonglong2*>(sW)[i] = reinterpret_cast<const ulonglong2*>(W1)[i];
    __syncthreads();

    int row = blockIdx.x * 256 + threadIdx.x;
    if (row >= N_NODES) return;

    unsigned long long acc[HID_CH / 2];
#pragma unroll
    for (int i = 0; i < HID_CH / 2; i++) acc[i] = 0ull;

    const float4* xr = reinterpret_cast<const float4*>(x + (size_t)row * IN_CH);
    for (int kk = 0; kk < IN_CH / 4; kk++) {
        float4 xv = __ldg(xr + kk);
#pragma unroll
        for (int j = 0; j < 4; j++) {
            float xs = (j == 0) ? xv.x : (j == 1) ? xv.y : (j == 2) ? xv.z : xv.w;
            unsigned long long xx = pack2(xs, xs);
            int k = kk * 4 + j;
#pragma unroll
            for (int c4 = 0; c4 < HID_CH / 4; c4++) {
                ulonglong2 w = sW[k][c4];
                acc[2 * c4 + 0] = fma2(xx, w.x, acc[2 * c4 + 0]);
                acc[2 * c4 + 1] = fma2(xx, w.y, acc[2 * c4 + 1]);
            }
        }
    }
    ulonglong2* o = reinterpret_cast<ulonglong2*>(g_h1 + (size_t)row * HID_CH);
#pragma unroll
    for (int c4 = 0; c4 < HID_CH / 4; c4++) {
        ulonglong2 v; v.x = acc[2 * c4]; v.y = acc[2 * c4 + 1];
        o[c4] = v;
    }
}

// ---- fused agg1 + gemm2: m2 = relu(A @ h1 + b1) @ W2, warp per node ----
__global__ __launch_bounds__(256) void k_agg1g2(const float* __restrict__ b1,
                                                const float* __restrict__ W2) {
    __shared__ float sW2[HID_CH * CLS_CH];   // 8 KB, row-major [k][c]
    for (int i = threadIdx.x; i < HID_CH * CLS_CH; i += 256)
        sW2[i] = W2[i];
    __syncthreads();

    int t = blockIdx.x * 256 + threadIdx.x;
    int node = t >> 5;
    if (node >= N_NODES) return;
    int lane = t & 31;

    int beg = g_off[node];
    int dg  = g_deg[node];

    // gather-sum h1 rows: lane holds channels 2*lane, 2*lane+1
    float2 acc = make_float2(0.f, 0.f);
    for (int base = 0; base < dg; base += 32) {
        int idx = (base + lane < dg) ? __ldg(g_csr_src + beg + base + lane) : 0;
        int cnt = min(32, dg - base);
        for (int k = 0; k < cnt; k++) {
            int s = __shfl_sync(0xffffffffu, idx, k);
            float2 v = __ldg(reinterpret_cast<const float2*>(g_h1) + (size_t)s * 32 + lane);
            acc.x += v.x;
            acc.y += v.y;
        }
    }
    float2 b = reinterpret_cast<const float2*>(b1)[lane];
    acc.x = fmaxf(acc.x + b.x, 0.f);
    acc.y = fmaxf(acc.y + b.y, 0.f);

    // fused gemm2: m2[node][lane] = sum_k act[k] * W2[k][lane]
    float oacc = 0.f;
#pragma unroll
    for (int j = 0; j < 32; j++) {
        float ax = __shfl_sync(0xffffffffu, acc.x, j);   // act ch 2j
        float ay = __shfl_sync(0xffffffffu, acc.y, j);   // act ch 2j+1
        oacc = fmaf(ax, sW2[(2 * j) * CLS_CH + lane], oacc);
        oacc = fmaf(ay, sW2[(2 * j + 1) * CLS_CH + lane], oacc);
    }
    g_m2[(size_t)node * CLS_CH + lane] = oacc;
}

// ---------------- agg2: out = sigmoid(A @ m2 + b2), warp per node (R2-proven) ----------------
__global__ __launch_bounds__(256) void k_agg2(const float* __restrict__ b2,
                                              float* __restrict__ out) {
    int t = blockIdx.x * 256 + threadIdx.x;
    int node = t >> 5;
    if (node >= N_NODES) return;
    int lane = t & 31;

    int beg = g_off[node];
    int dg  = g_deg[node];

    float acc = 0.f;
    for (int base = 0; base < dg; base += 32) {
        int idx = (base + lane < dg) ? __ldg(g_csr_src + beg + base + lane) : 0;
        int cnt = min(32, dg - base);
        for (int k = 0; k < cnt; k++) {
            int s = __shfl_sync(0xffffffffu, idx, k);
            acc += __ldg(g_m2 + (size_t)s * CLS_CH + lane);
        }
    }
    float v = acc + __ldg(b2 + lane);
    out[(size_t)node * CLS_CH + lane] = 1.f / (1.f + __expf(-v));
}

extern "C" void kernel_launch(void* const* d_in, const int* in_sizes, int n_in,
                              void* d_out, int out_size) {
    const float* x  = (const float*)d_in[0];
    const int*   ei = (const int*)  d_in[1];
    const float* W1 = (const float*)d_in[2];
    const float* b1 = (const float*)d_in[3];
    const float* W2 = (const float*)d_in[4];
    const float* b2 = (const float*)d_in[5];
    float* out = (float*)d_out;
    const int* src = ei;
    const int* dst = ei + N_EDGES;

    // gemm1 hoisted to launch index 3 (it is independent of scan/fill) so the
    // profiler's fixed launch-skip lands on it this round.
    k_zero_cnt<<<(N_NODES + 255) / 256, 256>>>();
    k_hist<<<(N_EDGES + 255) / 256, 256>>>(dst);
    k_scan1<<<NB, SCAN_B>>>();
    k_gemm1<<<(N_NODES + 255) / 256, 256>>>(x, W1);          // <- profiled
    k_scan23<<<NB, SCAN_B>>>();
    k_fill<<<(N_EDGES + 255) / 256, 256>>>(src, dst);

    k_agg1g2<<<(N_NODES * 32 + 255) / 256, 256>>>(b1, W2);
    k_agg2<<<(N_NODES * 32 + 255) / 256, 256>>>(b2, out);
}

// round 6
// speedup vs baseline: 1.5398x; 1.3057x over previous
#include <cuda_runtime.h>
#include <cstdint>

#define N_NODES 100000
#define N_EDGES 1250000
#define IN_CH   128
#define HID_CH  64
#define CLS_CH  32
#define SCAN_B  1024
#define NB      98        // ceil(N_NODES / SCAN_B)

// ---------------- scratch (device globals; alloc-free rule) ----------------
__device__ __align__(16) float g_h1  [(size_t)N_NODES * HID_CH];
__device__ __align__(16) float g_act1[(size_t)N_NODES * HID_CH];
__device__ __align__(16) float g_m2  [(size_t)N_NODES * CLS_CH];
__device__ int g_deg   [N_NODES];
__device__ int g_incl  [N_NODES];
__device__ int g_off   [N_NODES];
__device__ int g_cursor[N_NODES];
__device__ int g_bsum  [128];
__device__ int g_csr_src[N_EDGES];

// ---------------- packed f32x2 helpers ----------------
__device__ __forceinline__ unsigned long long pack2(float a, float b) {
    unsigned long long r;
    asm("mov.b64 %0, {%1, %2};" : "=l"(r) : "f"(a), "f"(b));
    return r;
}
__device__ __forceinline__ unsigned long long fma2(unsigned long long a,
                                                   unsigned long long b,
                                                   unsigned long long c) {
    unsigned long long d;
    asm("fma.rn.f32x2 %0, %1, %2, %3;" : "=l"(d) : "l"(a), "l"(b), "l"(c));
    return d;
}
__device__ __forceinline__ float2 ull2f2(unsigned long long u) {
    float2 f;
    asm("mov.b64 {%0, %1}, %2;" : "=f"(f.x), "=f"(f.y) : "l"(u));
    return f;
}

// ---------------- CSR build ----------------
__global__ void k_zero_cnt() {
    int i = blockIdx.x * blockDim.x + threadIdx.x;
    if (i < N_NODES) { g_deg[i] = 0; g_cursor[i] = 0; }
}

__global__ void k_hist(const int* __restrict__ dst) {
    int e = blockIdx.x * blockDim.x + threadIdx.x;
    if (e < N_EDGES) atomicAdd(&g_deg[__ldg(dst + e)], 1);
}

__global__ __launch_bounds__(SCAN_B) void k_scan1() {
    __shared__ int swarp[32];
    int tid = threadIdx.x;
    int lane = tid & 31, wid = tid >> 5;
    int i = blockIdx.x * SCAN_B + tid;
    int v = (i < N_NODES) ? g_deg[i] : 0;
    int x = v;
#pragma unroll
    for (int o = 1; o < 32; o <<= 1) {
        int n = __shfl_up_sync(0xffffffffu, x, o);
        if (lane >= o) x += n;
    }
    if (lane == 31) swarp[wid] = x;
    __syncthreads();
    if (wid == 0) {
        int w = swarp[lane];
#pragma unroll
        for (int o = 1; o < 32; o <<= 1) {
            int n = __shfl_up_sync(0xffffffffu, w, o);
            if (lane >= o) w += n;
        }
        swarp[lane] = w;
    }
    __syncthreads();
    int incl = x + (wid > 0 ? swarp[wid - 1] : 0);
    if (i < N_NODES) g_incl[i] = incl;
    if (tid == SCAN_B - 1) g_bsum[blockIdx.x] = incl;
}

__global__ __launch_bounds__(SCAN_B) void k_scan23() {
    __shared__ int sred[32];
    __shared__ int s_base;
    int tid = threadIdx.x;
    int v = (tid < blockIdx.x) ? g_bsum[tid] : 0;
#pragma unroll
    for (int o = 16; o; o >>= 1) v += __shfl_down_sync(0xffffffffu, v, o);
    if ((tid & 31) == 0) sred[tid >> 5] = v;
    __syncthreads();
    if (tid < 32) {
        int w = sred[tid];
#pragma unroll
        for (int o = 16; o; o >>= 1) w += __shfl_down_sync(0xffffffffu, w, o);
        if (tid == 0) s_base = w;
    }
    __syncthreads();
    int i = blockIdx.x * SCAN_B + tid;
    if (i < N_NODES) g_off[i] = g_incl[i] - g_deg[i] + s_base;
}

__global__ void k_fill(const int* __restrict__ src, const int* __restrict__ dst) {
    int e = blockIdx.x * blockDim.x + threadIdx.x;
    if (e >= N_EDGES) return;
    int d = __ldg(dst + e);
    int pos = atomicAdd(&g_cursor[d], 1);
    g_csr_src[g_off[d] + pos] = __ldg(src + e);
}

// ---------------- gemm1: h1 = x @ W1 (128->64), register-tiled ----------------
// block tile 128x64, BK=16, 256 threads, thread tile 8 rows x 4 cols
#define BM 128
#define BK 16
#define SA_PAD 136   // 128 + 8 floats; 136*4=544B row stride (16B aligned)
__global__ __launch_bounds__(256) void k_gemm1(const float* __restrict__ x,
                                               const float* __restrict__ W1) {
    __shared__ __align__(16) float sA[BK][SA_PAD];       // 8.7 KB, k-major
    __shared__ __align__(16) float sW[BK][HID_CH];       // 4 KB
    int tid = threadIdx.x;
    int tx = tid & 15;         // cols tx*4 .. +3
    int ty = tid >> 4;         // rows ty*8 .. +7
    int row0 = blockIdx.x * BM;

    unsigned long long acc[4][4];   // [rowpair][col]
#pragma unroll
    for (int i = 0; i < 4; i++)
#pragma unroll
        for (int j = 0; j < 4; j++) acc[i][j] = 0ull;

#pragma unroll 1
    for (int ch = 0; ch < IN_CH / BK; ch++) {
        __syncthreads();
        {   // A tile: 128 rows x 16 cols, transposed store into k-major
            int r = tid >> 2, c4 = tid & 3;
#pragma unroll
            for (int j = 0; j < 2; j++) {
                int rr = r + j * 64;
                int gr = min(row0 + rr, N_NODES - 1);
                float4 v = __ldg(reinterpret_cast<const float4*>(
                                     x + (size_t)gr * IN_CH + ch * BK) + c4);
                sA[c4 * 4 + 0][rr] = v.x;
                sA[c4 * 4 + 1][rr] = v.y;
                sA[c4 * 4 + 2][rr] = v.z;
                sA[c4 * 4 + 3][rr] = v.w;
            }
        }
        {   // W tile: 16 k x 64 ch
            int k = tid >> 4, c4 = tid & 15;
            float4 w = __ldg(reinterpret_cast<const float4*>(
                                 W1 + (size_t)(ch * BK + k) * HID_CH) + c4);
            *reinterpret_cast<float4*>(&sW[k][c4 * 4]) = w;
        }
        __syncthreads();
#pragma unroll
        for (int k = 0; k < BK; k++) {
            ulonglong2 aA = *reinterpret_cast<const ulonglong2*>(&sA[k][ty * 8]);
            ulonglong2 aB = *reinterpret_cast<const ulonglong2*>(&sA[k][ty * 8 + 4]);
            float4 wv = *reinterpret_cast<const float4*>(&sW[k][tx * 4]);
            unsigned long long w0 = pack2(wv.x, wv.x);
            unsigned long long w1 = pack2(wv.y, wv.y);
            unsigned long long w2 = pack2(wv.z, wv.z);
            unsigned long long w3 = pack2(wv.w, wv.w);
            acc[0][0] = fma2(aA.x, w0, acc[0][0]);
            acc[0][1] = fma2(aA.x, w1, acc[0][1]);
            acc[0][2] = fma2(aA.x, w2, acc[0][2]);
            acc[0][3] = fma2(aA.x, w3, acc[0][3]);
            acc[1][0] = fma2(aA.y, w0, acc[1][0]);
            acc[1][1] = fma2(aA.y, w1, acc[1][1]);
            acc[1][2] = fma2(aA.y, w2, acc[1][2]);
            acc[1][3] = fma2(aA.y, w3, acc[1][3]);
            acc[2][0] = fma2(aB.x, w0, acc[2][0]);
            acc[2][1] = fma2(aB.x, w1, acc[2][1]);
            acc[2][2] = fma2(aB.x, w2, acc[2][2]);
            acc[2][3] = fma2(aB.x, w3, acc[2][3]);
            acc[3][0] = fma2(aB.y, w0, acc[3][0]);
            acc[3][1] = fma2(aB.y, w1, acc[3][1]);
            acc[3][2] = fma2(aB.y, w2, acc[3][2]);
            acc[3][3] = fma2(aB.y, w3, acc[3][3]);
        }
    }
#pragma unroll
    for (int rp = 0; rp < 4; rp++) {
        int r = row0 + ty * 8 + rp * 2;
        float2 c0 = ull2f2(acc[rp][0]), c1 = ull2f2(acc[rp][1]);
        float2 c2 = ull2f2(acc[rp][2]), c3 = ull2f2(acc[rp][3]);
        if (r < N_NODES) {
            float4 lo = make_float4(c0.x, c1.x, c2.x, c3.x);
            *reinterpret_cast<float4*>(g_h1 + (size_t)r * HID_CH + tx * 4) = lo;
        }
        if (r + 1 < N_NODES) {
            float4 hi = make_float4(c0.y, c1.y, c2.y, c3.y);
            *reinterpret_cast<float4*>(g_h1 + (size_t)(r + 1) * HID_CH + tx * 4) = hi;
        }
    }
}

// ---------------- agg1: act1 = relu(A @ h1 + b1), warp/node, MLP-8 ----------------
__device__ __forceinline__ float2 ld2(int s, int lane) {
    return __ldg(reinterpret_cast<const float2*>(g_h1) + (size_t)s * 32 + lane);
}
__global__ __launch_bounds__(256) void k_agg1(const float* __restrict__ b1) {
    int t = blockIdx.x * 256 + threadIdx.x;
    int node = t >> 5;
    if (node >= N_NODES) return;
    int lane = t & 31;

    int beg = g_off[node];
    int dg  = g_deg[node];

    float2 a0{0,0}, a1{0,0}, a2{0,0}, a3{0,0}, a4{0,0}, a5{0,0}, a6{0,0}, a7{0,0};
    for (int base = 0; base < dg; base += 32) {
        int rem = dg - base;
        int idx = 0;
        if (lane < rem) idx = __ldg(g_csr_src + beg + base + lane);
#pragma unroll
        for (int k = 0; k < 32; k += 8) {
            if (k >= rem) break;
            int s0 = __shfl_sync(0xffffffffu, idx, k + 0);
            int s1 = __shfl_sync(0xffffffffu, idx, k + 1);
            int s2 = __shfl_sync(0xffffffffu, idx, k + 2);
            int s3 = __shfl_sync(0xffffffffu, idx, k + 3);
            int s4 = __shfl_sync(0xffffffffu, idx, k + 4);
            int s5 = __shfl_sync(0xffffffffu, idx, k + 5);
            int s6 = __shfl_sync(0xffffffffu, idx, k + 6);
            int s7 = __shfl_sync(0xffffffffu, idx, k + 7);
            { float2 v = ld2(s0, lane); a0.x += v.x; a0.y += v.y; }
            if (k + 1 < rem) { float2 v = ld2(s1, lane); a1.x += v.x; a1.y += v.y; }
            if (k + 2 < rem) { float2 v = ld2(s2, lane); a2.x += v.x; a2.y += v.y; }
            if (k + 3 < rem) { float2 v = ld2(s3, lane); a3.x += v.x; a3.y += v.y; }
            if (k + 4 < rem) { float2 v = ld2(s4, lane); a4.x += v.x; a4.y += v.y; }
            if (k + 5 < rem) { float2 v = ld2(s5, lane); a5.x += v.x; a5.y += v.y; }
            if (k + 6 < rem) { float2 v = ld2(s6, lane); a6.x += v.x; a6.y += v.y; }
            if (k + 7 < rem) { float2 v = ld2(s7, lane); a7.x += v.x; a7.y += v.y; }
        }
    }
    float2 acc;
    acc.x = ((a0.x + a1.x) + (a2.x + a3.x)) + ((a4.x + a5.x) + (a6.x + a7.x));
    acc.y = ((a0.y + a1.y) + (a2.y + a3.y)) + ((a4.y + a5.y) + (a6.y + a7.y));
    float2 b = reinterpret_cast<const float2*>(b1)[lane];
    acc.x = fmaxf(acc.x + b.x, 0.f);
    acc.y = fmaxf(acc.y + b.y, 0.f);
    reinterpret_cast<float2*>(g_act1 + (size_t)node * HID_CH)[lane] = acc;
}

// ---------------- gemm2: m2 = act1 @ W2 (64->32), register-tiled ----------------
// block tile 128x32, BK=16, 256 threads, thread tile 8 rows x 2 cols
__global__ __launch_bounds__(256) void k_gemm2(const float* __restrict__ W2) {
    __shared__ __align__(16) float sA[BK][SA_PAD];       // 8.7 KB
    __shared__ __align__(16) float sW[BK][CLS_CH];       // 2 KB
    int tid = threadIdx.x;
    int tx = tid & 15;         // cols tx*2, tx*2+1
    int ty = tid >> 4;         // rows ty*8 .. +7
    int row0 = blockIdx.x * BM;

    unsigned long long acc[4][2];
#pragma unroll
    for (int i = 0; i < 4; i++) { acc[i][0] = 0ull; acc[i][1] = 0ull; }

#pragma unroll 1
    for (int ch = 0; ch < HID_CH / BK; ch++) {
        __syncthreads();
        {   // A tile: 128 rows x 16 cols from g_act1
            int r = tid >> 2, c4 = tid & 3;
#pragma unroll
            for (int j = 0; j < 2; j++) {
                int rr = r + j * 64;
                int gr = min(row0 + rr, N_NODES - 1);
                float4 v = *reinterpret_cast<const float4*>(
                    g_act1 + (size_t)gr * HID_CH + ch * BK + c4 * 4);
                sA[c4 * 4 + 0][rr] = v.x;
                sA[c4 * 4 + 1][rr] = v.y;
                sA[c4 * 4 + 2][rr] = v.z;
                sA[c4 * 4 + 3][rr] = v.w;
            }
        }
        if (tid < 128) {   // W tile: 16 k x 32 ch
            int k = tid >> 3, c4 = tid & 7;
            float4 w = __ldg(reinterpret_cast<const float4*>(
                                 W2 + (size_t)(ch * BK + k) * CLS_CH) + c4);
            *reinterpret_cast<float4*>(&sW[k][c4 * 4]) = w;
        }
        __syncthreads();
#pragma unroll
        for (int k = 0; k < BK; k++) {
            ulonglong2 aA = *reinterpret_cast<const ulonglong2*>(&sA[k][ty * 8]);
            ulonglong2 aB = *reinterpret_cast<const ulonglong2*>(&sA[k][ty * 8 + 4]);
            float2 wv = *reinterpret_cast<const float2*>(&sW[k][tx * 2]);
            unsigned long long w0 = pack2(wv.x, wv.x);
            unsigned long long w1 = pack2(wv.y, wv.y);
            acc[0][0] = fma2(aA.x, w0, acc[0][0]);
            acc[0][1] = fma2(aA.x, w1, acc[0][1]);
            acc[1][0] = fma2(aA.y, w0, acc[1][0]);
            acc[1][1] = fma2(aA.y, w1, acc[1][1]);
            acc[2][0] = fma2(aB.x, w0, acc[2][0]);
            acc[2][1] = fma2(aB.x, w1, acc[2][1]);
            acc[3][0] = fma2(aB.y, w0, acc[3][0]);
            acc[3][1] = fma2(aB.y, w1, acc[3][1]);
        }
    }
#pragma unroll
    for (int rp = 0; rp < 4; rp++) {
        int r = row0 + ty * 8 + rp * 2;
        float2 c0 = ull2f2(acc[rp][0]), c1 = ull2f2(acc[rp][1]);
        if (r < N_NODES) {
            float2 lo = make_float2(c0.x, c1.x);
            *reinterpret_cast<float2*>(g_m2 + (size_t)r * CLS_CH + tx * 2) = lo;
        }
        if (r + 1 < N_NODES) {
            float2 hi = make_float2(c0.y, c1.y);
            *reinterpret_cast<float2*>(g_m2 + (size_t)(r + 1) * CLS_CH + tx * 2) = hi;
        }
    }
}

// ---------------- agg2: out = sigmoid(A @ m2 + b2), warp/node, MLP-8 ----------------
__global__ __launch_bounds__(256) void k_agg2(const float* __restrict__ b2,
                                              float* __restrict__ out) {
    int t = blockIdx.x * 256 + threadIdx.x;
    int node = t >> 5;
    if (node >= N_NODES) return;
    int lane = t & 31;

    int beg = g_off[node];
    int dg  = g_deg[node];

    float a0 = 0.f, a1 = 0.f, a2 = 0.f, a3 = 0.f, a4 = 0.f, a5 = 0.f, a6 = 0.f, a7 = 0.f;
    for (int base = 0; base < dg; base += 32) {
        int rem = dg - base;
        int idx = 0;
        if (lane < rem) idx = __ldg(g_csr_src + beg + base + lane);
#pragma unroll
        for (int k = 0; k < 32; k += 8) {
            if (k >= rem) break;
            int s0 = __shfl_sync(0xffffffffu, idx, k + 0);
            int s1 = __shfl_sync(0xffffffffu, idx, k + 1);
            int s2 = __shfl_sync(0xffffffffu, idx, k + 2);
            int s3 = __shfl_sync(0xffffffffu, idx, k + 3);
            int s4 = __shfl_sync(0xffffffffu, idx, k + 4);
            int s5 = __shfl_sync(0xffffffffu, idx, k + 5);
            int s6 = __shfl_sync(0xffffffffu, idx, k + 6);
            int s7 = __shfl_sync(0xffffffffu, idx, k + 7);
            a0 += __ldg(g_m2 + (size_t)s0 * CLS_CH + lane);
            if (k + 1 < rem) a1 += __ldg(g_m2 + (size_t)s1 * CLS_CH + lane);
            if (k + 2 < rem) a2 += __ldg(g_m2 + (size_t)s2 * CLS_CH + lane);
            if (k + 3 < rem) a3 += __ldg(g_m2 + (size_t)s3 * CLS_CH + lane);
            if (k + 4 < rem) a4 += __ldg(g_m2 + (size_t)s4 * CLS_CH + lane);
            if (k + 5 < rem) a5 += __ldg(g_m2 + (size_t)s5 * CLS_CH + lane);
            if (k + 6 < rem) a6 += __ldg(g_m2 + (size_t)s6 * CLS_CH + lane);
            if (k + 7 < rem) a7 += __ldg(g_m2 + (size_t)s7 * CLS_CH + lane);
        }
    }
    float acc = ((a0 + a1) + (a2 + a3)) + ((a4 + a5) + (a6 + a7));
    float v = acc + __ldg(b2 + lane);
    out[(size_t)node * CLS_CH + lane] = 1.f / (1.f + __expf(-v));
}

extern "C" void kernel_launch(void* const* d_in, const int* in_sizes, int n_in,
                              void* d_out, int out_size) {
    const float* x  = (const float*)d_in[0];
    const int*   ei = (const int*)  d_in[1];
    const float* W1 = (const float*)d_in[2];
    const float* b1 = (const float*)d_in[3];
    const float* W2 = (const float*)d_in[4];
    const float* b2 = (const float*)d_in[5];
    float* out = (float*)d_out;
    const int* src = ei;
    const int* dst = ei + N_EDGES;

    k_zero_cnt<<<(N_NODES + 255) / 256, 256>>>();
    k_hist<<<(N_EDGES + 255) / 256, 256>>>(dst);
    k_scan1<<<NB, SCAN_B>>>();
    k_gemm1<<<(N_NODES + BM - 1) / BM, 256>>>(x, W1);     // <- profiled (idx 3)
    k_scan23<<<NB, SCAN_B>>>();
    k_fill<<<(N_EDGES + 255) / 256, 256>>>(src, dst);

    k_agg1<<<(N_NODES * 32 + 255) / 256, 256>>>(b1);
    k_gemm2<<<(N_NODES + BM - 1) / BM, 256>>>(W2);
    k_agg2<<<(N_NODES * 32 + 255) / 256, 256>>>(b2, out);
}

// round 8
// speedup vs baseline: 1.5750x; 1.0229x over previous
#include <cuda_runtime.h>
#include <cstdint>

#define N_NODES 100000
#define N_EDGES 1250000
#define IN_CH   128
#define HID_CH  64
#define CLS_CH  32
#define SCAN_B  1024
#define NB      98        // ceil(N_NODES / SCAN_B)

// ---------------- scratch (device globals; alloc-free rule) ----------------
__device__ __align__(16) float g_h1  [(size_t)N_NODES * HID_CH];
__device__ __align__(16) float g_act1[(size_t)N_NODES * HID_CH];
__device__ __align__(16) float g_m2  [(size_t)N_NODES * CLS_CH];
__device__ int g_deg   [N_NODES];
__device__ int g_incl  [N_NODES];
__device__ int g_off   [N_NODES];
__device__ int g_cursor[N_NODES];
__device__ int g_bsum  [128];
__device__ int g_csr_src[N_EDGES];

// ---------------- packed f32x2 helpers ----------------
__device__ __forceinline__ unsigned long long pack2(float a, float b) {
    unsigned long long r;
    asm("mov.b64 %0, {%1, %2};" : "=l"(r) : "f"(a), "f"(b));
    return r;
}
__device__ __forceinline__ unsigned long long fma2(unsigned long long a,
                                                   unsigned long long b,
                                                   unsigned long long c) {
    unsigned long long d;
    asm("fma.rn.f32x2 %0, %1, %2, %3;" : "=l"(d) : "l"(a), "l"(b), "l"(c));
    return d;
}
__device__ __forceinline__ float2 ull2f2(unsigned long long u) {
    float2 f;
    asm("mov.b64 {%0, %1}, %2;" : "=f"(f.x), "=f"(f.y) : "l"(u));
    return f;
}

// ---------------- CSR build ----------------
__global__ void k_zero_cnt() {
    int i = blockIdx.x * blockDim.x + threadIdx.x;
    if (i < N_NODES) g_deg[i] = 0;
}

__global__ void k_hist(const int* __restrict__ dst) {
    int e = blockIdx.x * blockDim.x + threadIdx.x;
    if (e < N_EDGES) atomicAdd(&g_deg[__ldg(dst + e)], 1);
}

__global__ __launch_bounds__(SCAN_B) void k_scan1() {
    __shared__ int swarp[32];
    int tid = threadIdx.x;
    int lane = tid & 31, wid = tid >> 5;
    int i = blockIdx.x * SCAN_B + tid;
    int v = (i < N_NODES) ? g_deg[i] : 0;
    int x = v;
#pragma unroll
    for (int o = 1; o < 32; o <<= 1) {
        int n = __shfl_up_sync(0xffffffffu, x, o);
        if (lane >= o) x += n;
    }
    if (lane == 31) swarp[wid] = x;
    __syncthreads();
    if (wid == 0) {
        int w = swarp[lane];
#pragma unroll
        for (int o = 1; o < 32; o <<= 1) {
            int n = __shfl_up_sync(0xffffffffu, w, o);
            if (lane >= o) w += n;
        }
        swarp[lane] = w;
    }
    __syncthreads();
    int incl = x + (wid > 0 ? swarp[wid - 1] : 0);
    if (i < N_NODES) g_incl[i] = incl;
    if (tid == SCAN_B - 1) g_bsum[blockIdx.x] = incl;
}

// offsets + cursor primed to offset (k_fill then needs no g_off load)
__global__ __launch_bounds__(SCAN_B) void k_scan23() {
    __shared__ int sred[32];
    __shared__ int s_base;
    int tid = threadIdx.x;
    int v = (tid < blockIdx.x) ? g_bsum[tid] : 0;
#pragma unroll
    for (int o = 16; o; o >>= 1) v += __shfl_down_sync(0xffffffffu, v, o);
    if ((tid & 31) == 0) sred[tid >> 5] = v;
    __syncthreads();
    if (tid < 32) {
        int w = sred[tid];
#pragma unroll
        for (int o = 16; o; o >>= 1) w += __shfl_down_sync(0xffffffffu, w, o);
        if (tid == 0) s_base = w;
    }
    __syncthreads();
    int i = blockIdx.x * SCAN_B + tid;
    if (i < N_NODES) {
        int off = g_incl[i] - g_deg[i] + s_base;
        g_off[i] = off;
        g_cursor[i] = off;
    }
}

__global__ void k_fill(const int* __restrict__ src, const int* __restrict__ dst) {
    int e = blockIdx.x * blockDim.x + threadIdx.x;
    if (e >= N_EDGES) return;
    int d = __ldg(dst + e);
    int pos = atomicAdd(&g_cursor[d], 1);
    g_csr_src[pos] = __ldg(src + e);
}

// ---------------- gemm1: h1 = x @ W1 (128->64), double-buffered ----------------
// block tile 128x64, BK=16, 256 threads, thread tile 8 rows x 4 cols
#define BM 128
#define BK 16
#define SA_PAD 136   // 128 + 8 floats; 544B row stride (16B aligned)
__global__ __launch_bounds__(256) void k_gemm1(const float* __restrict__ x,
                                               const float* __restrict__ W1) {
    __shared__ __align__(16) float sA[2][BK][SA_PAD];    // 17.4 KB, k-major
    __shared__ __align__(16) float sW[2][BK][HID_CH];    // 8 KB
    int tid = threadIdx.x;
    int tx = tid & 15;         // cols tx*4 .. +3
    int ty = tid >> 4;         // rows ty*8 .. +7
    int row0 = blockIdx.x * BM;
    int ar = tid >> 2, ac4 = tid & 3;   // A-loader coords
    int wk = tid >> 4, wc4 = tid & 15;  // W-loader coords
    int gr0 = min(row0 + ar,      N_NODES - 1);
    int gr1 = min(row0 + ar + 64, N_NODES - 1);
    const float4* xr0 = reinterpret_cast<const float4*>(x + (size_t)gr0 * IN_CH) + ac4;
    const float4* xr1 = reinterpret_cast<const float4*>(x + (size_t)gr1 * IN_CH) + ac4;

    float4 pa0, pa1, pw;
    pa0 = __ldg(xr0);
    pa1 = __ldg(xr1);
    pw  = __ldg(reinterpret_cast<const float4*>(W1 + (size_t)wk * HID_CH) + wc4);

    unsigned long long acc[4][4];
#pragma unroll
    for (int i = 0; i < 4; i++)
#pragma unroll
        for (int j = 0; j < 4; j++) acc[i][j] = 0ull;

#pragma unroll 1
    for (int ch = 0; ch < IN_CH / BK; ch++) {
        int s = ch & 1;
        // store prefetched chunk (transposed A)
        sA[s][ac4 * 4 + 0][ar] = pa0.x;
        sA[s][ac4 * 4 + 1][ar] = pa0.y;
        sA[s][ac4 * 4 + 2][ar] = pa0.z;
        sA[s][ac4 * 4 + 3][ar] = pa0.w;
        sA[s][ac4 * 4 + 0][ar + 64] = pa1.x;
        sA[s][ac4 * 4 + 1][ar + 64] = pa1.y;
        sA[s][ac4 * 4 + 2][ar + 64] = pa1.z;
        sA[s][ac4 * 4 + 3][ar + 64] = pa1.w;
        *reinterpret_cast<float4*>(&sW[s][wk][wc4 * 4]) = pw;
        __syncthreads();
        if (ch < IN_CH / BK - 1) {   // issue next chunk's loads; overlap with compute
            int kofs = (ch + 1) * BK;
            pa0 = __ldg(xr0 + kofs / 4);
            pa1 = __ldg(xr1 + kofs / 4);
            pw  = __ldg(reinterpret_cast<const float4*>(
                            W1 + (size_t)(kofs + wk) * HID_CH) + wc4);
        }
#pragma unroll
        for (int k = 0; k < BK; k++) {
            ulonglong2 aA = *reinterpret_cast<const ulonglong2*>(&sA[s][k][ty * 8]);
            ulonglong2 aB = *reinterpret_cast<const ulonglong2*>(&sA[s][k][ty * 8 + 4]);
            float4 wv = *reinterpret_cast<const float4*>(&sW[s][k][tx * 4]);
            unsigned long long w0 = pack2(wv.x, wv.x);
            unsigned long long w1 = pack2(wv.y, wv.y);
            unsigned long long w2 = pack2(wv.z, wv.z);
            unsigned long long w3 = pack2(wv.w, wv.w);
            acc[0][0] = fma2(aA.x, w0, acc[0][0]);
            acc[0][1] = fma2(aA.x, w1, acc[0][1]);
            acc[0][2] = fma2(aA.x, w2, acc[0][2]);
            acc[0][3] = fma2(aA.x, w3, acc[0][3]);
            acc[1][0] = fma2(aA.y, w0, acc[1][0]);
            acc[1][1] = fma2(aA.y, w1, acc[1][1]);
            acc[1][2] = fma2(aA.y, w2, acc[1][2]);
            acc[1][3] = fma2(aA.y, w3, acc[1][3]);
            acc[2][0] = fma2(aB.x, w0, acc[2][0]);
            acc[2][1] = fma2(aB.x, w1, acc[2][1]);
            acc[2][2] = fma2(aB.x, w2, acc[2][2]);
            acc[2][3] = fma2(aB.x, w3, acc[2][3]);
            acc[3][0] = fma2(aB.y, w0, acc[3][0]);
            acc[3][1] = fma2(aB.y, w1, acc[3][1]);
            acc[3][2] = fma2(aB.y, w2, acc[3][2]);
            acc[3][3] = fma2(aB.y, w3, acc[3][3]);
        }
    }
#pragma unroll
    for (int rp = 0; rp < 4; rp++) {
        int r = row0 + ty * 8 + rp * 2;
        float2 c0 = ull2f2(acc[rp][0]), c1 = ull2f2(acc[rp][1]);
        float2 c2 = ull2f2(acc[rp][2]), c3 = ull2f2(acc[rp][3]);
        if (r < N_NODES) {
            float4 lo = make_float4(c0.x, c1.x, c2.x, c3.x);
            *reinterpret_cast<float4*>(g_h1 + (size_t)r * HID_CH + tx * 4) = lo;
        }
        if (r + 1 < N_NODES) {
            float4 hi = make_float4(c0.y, c1.y, c2.y, c3.y);
            *reinterpret_cast<float4*>(g_h1 + (size_t)(r + 1) * HID_CH + tx * 4) = hi;
        }
    }
}

// ---------------- agg1: act1 = relu(A @ h1 + b1), warp/node, MLP-8 ----------------
__device__ __forceinline__ float2 ld2(int s, int lane) {
    return __ldg(reinterpret_cast<const float2*>(g_h1) + (size_t)s * 32 + lane);
}
__global__ __launch_bounds__(256) void k_agg1(const float* __restrict__ b1) {
    int t = blockIdx.x * 256 + threadIdx.x;
    int node = t >> 5;
    if (node >= N_NODES) return;
    int lane = t & 31;

    int beg = g_off[node];
    int dg  = g_deg[node];

    float2 a0{0,0}, a1{0,0}, a2{0,0}, a3{0,0}, a4{0,0}, a5{0,0}, a6{0,0}, a7{0,0};
    for (int base = 0; base < dg; base += 32) {
        int rem = dg - base;
        int idx = 0;
        if (lane < rem) idx = __ldg(g_csr_src + beg + base + lane);
#pragma unroll
        for (int k = 0; k < 32; k += 8) {
            if (k >= rem) break;
            int s0 = __shfl_sync(0xffffffffu, idx, k + 0);
            int s1 = __shfl_sync(0xffffffffu, idx, k + 1);
            int s2 = __shfl_sync(0xffffffffu, idx, k + 2);
            int s3 = __shfl_sync(0xffffffffu, idx, k + 3);
            int s4 = __shfl_sync(0xffffffffu, idx, k + 4);
            int s5 = __shfl_sync(0xffffffffu, idx, k + 5);
            int s6 = __shfl_sync(0xffffffffu, idx, k + 6);
            int s7 = __shfl_sync(0xffffffffu, idx, k + 7);
            { float2 v = ld2(s0, lane); a0.x += v.x; a0.y += v.y; }
            if (k + 1 < rem) { float2 v = ld2(s1, lane); a1.x += v.x; a1.y += v.y; }
            if (k + 2 < rem) { float2 v = ld2(s2, lane); a2.x += v.x; a2.y += v.y; }
            if (k + 3 < rem) { float2 v = ld2(s3, lane); a3.x += v.x; a3.y += v.y; }
            if (k + 4 < rem) { float2 v = ld2(s4, lane); a4.x += v.x; a4.y += v.y; }
            if (k + 5 < rem) { float2 v = ld2(s5, lane); a5.x += v.x; a5.y += v.y; }
            if (k + 6 < rem) { float2 v = ld2(s6, lane); a6.x += v.x; a6.y += v.y; }
            if (k + 7 < rem) { float2 v = ld2(s7, lane); a7.x += v.x; a7.y += v.y; }
        }
    }
    float2 acc;
    acc.x = ((a0.x + a1.x) + (a2.x + a3.x)) + ((a4.x + a5.x) + (a6.x + a7.x));
    acc.y = ((a0.y + a1.y) + (a2.y + a3.y)) + ((a4.y + a5.y) + (a6.y + a7.y));
    float2 b = reinterpret_cast<const float2*>(b1)[lane];
    acc.x = fmaxf(acc.x + b.x, 0.f);
    acc.y = fmaxf(acc.y + b.y, 0.f);
    reinterpret_cast<float2*>(g_act1 + (size_t)node * HID_CH)[lane] = acc;
}

// ---------------- gemm2: m2 = act1 @ W2 (64->32), double-buffered ----------------
__global__ __launch_bounds__(256) void k_gemm2(const float* __restrict__ W2) {
    __shared__ __align__(16) float sA[2][BK][SA_PAD];    // 17.4 KB
    __shared__ __align__(16) float sW[2][BK][CLS_CH];    // 4 KB
    int tid = threadIdx.x;
    int tx = tid & 15;         // cols tx*2, tx*2+1
    int ty = tid >> 4;         // rows ty*8 .. +7
    int row0 = blockIdx.x * BM;
    int ar = tid >> 2, ac4 = tid & 3;
    int wk = tid >> 3, wc4 = tid & 7;   // valid for tid < 128
    int gr0 = min(row0 + ar,      N_NODES - 1);
    int gr1 = min(row0 + ar + 64, N_NODES - 1);

    float4 pa0, pa1, pw;
    pa0 = *reinterpret_cast<const float4*>(g_act1 + (size_t)gr0 * HID_CH + ac4 * 4);
    pa1 = *reinterpret_cast<const float4*>(g_act1 + (size_t)gr1 * HID_CH + ac4 * 4);
    if (tid < 128)
        pw = __ldg(reinterpret_cast<const float4*>(W2 + (size_t)wk * CLS_CH) + wc4);

    unsigned long long acc[4][2];
#pragma unroll
    for (int i = 0; i < 4; i++) { acc[i][0] = 0ull; acc[i][1] = 0ull; }

#pragma unroll 1
    for (int ch = 0; ch < HID_CH / BK; ch++) {
        int s = ch & 1;
        sA[s][ac4 * 4 + 0][ar] = pa0.x;
        sA[s][ac4 * 4 + 1][ar] = pa0.y;
        sA[s][ac4 * 4 + 2][ar] = pa0.z;
        sA[s][ac4 * 4 + 3][ar] = pa0.w;
        sA[s][ac4 * 4 + 0][ar + 64] = pa1.x;
        sA[s][ac4 * 4 + 1][ar + 64] = pa1.y;
        sA[s][ac4 * 4 + 2][ar + 64] = pa1.z;
        sA[s][ac4 * 4 + 3][ar + 64] = pa1.w;
        if (tid < 128)
            *reinterpret_cast<float4*>(&sW[s][wk][wc4 * 4]) = pw;
        __syncthreads();
        if (ch < HID_CH / BK - 1) {
            int kofs = (ch + 1) * BK;
            pa0 = *reinterpret_cast<const float4*>(
                g_act1 + (size_t)gr0 * HID_CH + kofs + ac4 * 4);
            pa1 = *reinterpret_cast<const float4*>(
                g_act1 + (size_t)gr1 * HID_CH + kofs + ac4 * 4);
            if (tid < 128)
                pw = __ldg(reinterpret_cast<const float4*>(
                               W2 + (size_t)(kofs + wk) * CLS_CH) + wc4);
        }
#pragma unroll
        for (int k = 0; k < BK; k++) {
            ulonglong2 aA = *reinterpret_cast<const ulonglong2*>(&sA[s][k][ty * 8]);
            ulonglong2 aB = *reinterpret_cast<const ulonglong2*>(&sA[s][k][ty * 8 + 4]);
            float2 wv = *reinterpret_cast<const float2*>(&sW[s][k][tx * 2]);
            unsigned long long w0 = pack2(wv.x, wv.x);
            unsigned long long w1 = pack2(wv.y, wv.y);
            acc[0][0] = fma2(aA.x, w0, acc[0][0]);
            acc[0][1] = fma2(aA.x, w1, acc[0][1]);
            acc[1][0] = fma2(aA.y, w0, acc[1][0]);
            acc[1][1] = fma2(aA.y, w1, acc[1][1]);
            acc[2][0] = fma2(aB.x, w0, acc[2][0]);
            acc[2][1] = fma2(aB.x, w1, acc[2][1]);
            acc[3][0] = fma2(aB.y, w0, acc[3][0]);
            acc[3][1] = fma2(aB.y, w1, acc[3][1]);
        }
    }
#pragma unroll
    for (int rp = 0; rp < 4; rp++) {
        int r = row0 + ty * 8 + rp * 2;
        float2 c0 = ull2f2(acc[rp][0]), c1 = ull2f2(acc[rp][1]);
        if (r < N_NODES) {
            float2 lo = make_float2(c0.x, c1.x);
            *reinterpret_cast<float2*>(g_m2 + (size_t)r * CLS_CH + tx * 2) = lo;
        }
        if (r + 1 < N_NODES) {
            float2 hi = make_float2(c0.y, c1.y);
            *reinterpret_cast<float2*>(g_m2 + (size_t)(r + 1) * CLS_CH + tx * 2) = hi;
        }
    }
}

// ---------------- agg2: out = sigmoid(A @ m2 + b2), warp/node, MLP-8 ----------------
__global__ __launch_bounds__(256) void k_agg2(const float* __restrict__ b2,
                                              float* __restrict__ out) {
    int t = blockIdx.x * 256 + threadIdx.x;
    int node = t >> 5;
    if (node >= N_NODES) return;
    int lane = t & 31;

    int beg = g_off[node];
    int dg  = g_deg[node];

    float a0 = 0.f, a1 = 0.f, a2 = 0.f, a3 = 0.f, a4 = 0.f, a5 = 0.f, a6 = 0.f, a7 = 0.f;
    for (int base = 0; base < dg; base += 32) {
        int rem = dg - base;
        int idx = 0;
        if (lane < rem) idx = __ldg(g_csr_src + beg + base + lane);
#pragma unroll
        for (int k = 0; k < 32; k += 8) {
            if (k >= rem) break;
            int s0 = __shfl_sync(0xffffffffu, idx, k + 0);
            int s1 = __shfl_sync(0xffffffffu, idx, k + 1);
            int s2 = __shfl_sync(0xffffffffu, idx, k + 2);
            int s3 = __shfl_sync(0xffffffffu, idx, k + 3);
            int s4 = __shfl_sync(0xffffffffu, idx, k + 4);
            int s5 = __shfl_sync(0xffffffffu, idx, k + 5);
            int s6 = __shfl_sync(0xffffffffu, idx, k + 6);
            int s7 = __shfl_sync(0xffffffffu, idx, k + 7);
            a0 += __ldg(g_m2 + (size_t)s0 * CLS_CH + lane);
            if (k + 1 < rem) a1 += __ldg(g_m2 + (size_t)s1 * CLS_CH + lane);
            if (k + 2 < rem) a2 += __ldg(g_m2 + (size_t)s2 * CLS_CH + lane);
            if (k + 3 < rem) a3 += __ldg(g_m2 + (size_t)s3 * CLS_CH + lane);
            if (k + 4 < rem) a4 += __ldg(g_m2 + (size_t)s4 * CLS_CH + lane);
            if (k + 5 < rem) a5 += __ldg(g_m2 + (size_t)s5 * CLS_CH + lane);
            if (k + 6 < rem) a6 += __ldg(g_m2 + (size_t)s6 * CLS_CH + lane);
            if (k + 7 < rem) a7 += __ldg(g_m2 + (size_t)s7 * CLS_CH + lane);
        }
    }
    float acc = ((a0 + a1) + (a2 + a3)) + ((a4 + a5) + (a6 + a7));
    float v = acc + __ldg(b2 + lane);
    out[(size_t)node * CLS_CH + lane] = 1.f / (1.f + __expf(-v));
}

extern "C" void kernel_launch(void* const* d_in, const int* in_sizes, int n_in,
                              void* d_out, int out_size) {
    const float* x  = (const float*)d_in[0];
    const int*   ei = (const int*)  d_in[1];
    const float* W1 = (const float*)d_in[2];
    const float* b1 = (const float*)d_in[3];
    const float* W2 = (const float*)d_in[4];
    const float* b2 = (const float*)d_in[5];
    float* out = (float*)d_out;
    const int* src = ei;
    const int* dst = ei + N_EDGES;

    k_zero_cnt<<<(N_NODES + 255) / 256, 256>>>();
    k_hist<<<(N_EDGES + 255) / 256, 256>>>(dst);
    k_scan1<<<NB, SCAN_B>>>();
    k_gemm1<<<(N_NODES + BM - 1) / BM, 256>>>(x, W1);     // <- profiled (idx 3)
    k_scan23<<<NB, SCAN_B>>>();
    k_fill<<<(N_EDGES + 255) / 256, 256>>>(src, dst);

    k_agg1<<<(N_NODES * 32 + 255) / 256, 256>>>(b1);
    k_gemm2<<<(N_NODES + BM - 1) / BM, 256>>>(W2);
    k_agg2<<<(N_NODES * 32 + 255) / 256, 256>>>(b2, out);
}

// round 10
// speedup vs baseline: 1.6340x; 1.0375x over previous
#include <cuda_runtime.h>
#include <cstdint>

#define N_NODES 100000
#define N_EDGES 1250000
#define IN_CH   128
#define HID_CH  64
#define CLS_CH  32
#define SCAN_B  1024
#define NB      98        // ceil(N_NODES / SCAN_B)

// ---------------- scratch (device globals; alloc-free rule) ----------------
__device__ __align__(16) float g_h1  [(size_t)N_NODES * HID_CH];
__device__ __align__(16) float g_act1[(size_t)N_NODES * HID_CH];
__device__ __align__(16) float g_m2  [(size_t)N_NODES * CLS_CH];
__device__ int g_deg   [N_NODES];          // invariant: zero at kernel_launch entry
__device__ int g_incl  [N_NODES];
__device__ int g_off   [N_NODES + 1];
__device__ int g_cursor[N_NODES];
__device__ int g_bsum  [128];
__device__ int g_csr_src[N_EDGES];

// ---------------- packed f32x2 helpers ----------------
__device__ __forceinline__ unsigned long long pack2(float a, float b) {
    unsigned long long r;
    asm("mov.b64 %0, {%1, %2};" : "=l"(r) : "f"(a), "f"(b));
    return r;
}
__device__ __forceinline__ unsigned long long fma2(unsigned long long a,
                                                   unsigned long long b,
                                                   unsigned long long c) {
    unsigned long long d;
    asm("fma.rn.f32x2 %0, %1, %2, %3;" : "=l"(d) : "l"(a), "l"(b), "l"(c));
    return d;
}
__device__ __forceinline__ float2 ull2f2(unsigned long long u) {
    float2 f;
    asm("mov.b64 {%0, %1}, %2;" : "=f"(f.x), "=f"(f.y) : "l"(u));
    return f;
}

// ---------------- hist: degree histogram into pre-zeroed g_deg ----------------
__global__ void k_hist(const int* __restrict__ dst) {
    int e = blockIdx.x * blockDim.x + threadIdx.x;
    if (e < N_EDGES) atomicAdd(&g_deg[__ldg(dst + e)], 1);
}

// ---------------- scan1: per-block inclusive scan (warp-shuffle) ----------------
__global__ __launch_bounds__(SCAN_B) void k_scan1() {
    __shared__ int swarp[32];
    int tid = threadIdx.x;
    int lane = tid & 31, wid = tid >> 5;
    int i = blockIdx.x * SCAN_B + tid;
    int v = (i < N_NODES) ? g_deg[i] : 0;
    int x = v;
#pragma unroll
    for (int o = 1; o < 32; o <<= 1) {
        int n = __shfl_up_sync(0xffffffffu, x, o);
        if (lane >= o) x += n;
    }
    if (lane == 31) swarp[wid] = x;
    __syncthreads();
    if (wid == 0) {
        int w = swarp[lane];
#pragma unroll
        for (int o = 1; o < 32; o <<= 1) {
            int n = __shfl_up_sync(0xffffffffu, w, o);
            if (lane >= o) w += n;
        }
        swarp[lane] = w;
    }
    __syncthreads();
    int incl = x + (wid > 0 ? swarp[wid - 1] : 0);
    if (i < N_NODES) g_incl[i] = incl;
    if (tid == SCAN_B - 1) g_bsum[blockIdx.x] = incl;
}

// ---------------- scan23: block-base reduce + final offsets + cursor prime ----------------
__global__ __launch_bounds__(SCAN_B) void k_scan23() {
    __shared__ int sred[32];
    __shared__ int s_base;
    int tid = threadIdx.x;
    int v = (tid < blockIdx.x) ? g_bsum[tid] : 0;   // blockIdx.x <= 97 < 128
#pragma unroll
    for (int o = 16; o; o >>= 1) v += __shfl_down_sync(0xffffffffu, v, o);
    if ((tid & 31) == 0) sred[tid >> 5] = v;
    __syncthreads();
    if (tid < 32) {
        int w = sred[tid];
#pragma unroll
        for (int o = 16; o; o >>= 1) w += __shfl_down_sync(0xffffffffu, w, o);
        if (tid == 0) s_base = w;
    }
    __syncthreads();
    int i = blockIdx.x * SCAN_B + tid;
    if (i < N_NODES) {
        int d = g_deg[i];
        int off = g_incl[i] - d + s_base;
        g_off[i] = off;
        g_cursor[i] = off;
        if (i == N_NODES - 1) g_off[N_NODES] = off + d;
    }
}

// ---------------- fill: cursor pre-primed to offset ----------------
__global__ void k_fill(const int* __restrict__ src, const int* __restrict__ dst) {
    int e = blockIdx.x * blockDim.x + threadIdx.x;
    if (e >= N_EDGES) return;
    int d = __ldg(dst + e);
    int pos = atomicAdd(&g_cursor[d], 1);
    g_csr_src[pos] = __ldg(src + e);
}

// ---------------- gemm1: h1 = x @ W1 (128->64), double-buffered (R8-proven) ----------------
#define BM 128
#define BK 16
#define SA_PAD 136
__global__ __launch_bounds__(256) void k_gemm1(const float* __restrict__ x,
                                               const float* __restrict__ W1) {
    __shared__ __align__(16) float sA[2][BK][SA_PAD];
    __shared__ __align__(16) float sW[2][BK][HID_CH];
    int tid = threadIdx.x;
    int tx = tid & 15;
    int ty = tid >> 4;
    int row0 = blockIdx.x * BM;
    int ar = tid >> 2, ac4 = tid & 3;
    int wk = tid >> 4, wc4 = tid & 15;
    int gr0 = min(row0 + ar,      N_NODES - 1);
    int gr1 = min(row0 + ar + 64, N_NODES - 1);
    const float4* xr0 = reinterpret_cast<const float4*>(x + (size_t)gr0 * IN_CH) + ac4;
    const float4* xr1 = reinterpret_cast<const float4*>(x + (size_t)gr1 * IN_CH) + ac4;

    float4 pa0, pa1, pw;
    pa0 = __ldg(xr0);
    pa1 = __ldg(xr1);
    pw  = __ldg(reinterpret_cast<const float4*>(W1 + (size_t)wk * HID_CH) + wc4);

    unsigned long long acc[4][4];
#pragma unroll
    for (int i = 0; i < 4; i++)
#pragma unroll
        for (int j = 0; j < 4; j++) acc[i][j] = 0ull;

#pragma unroll 1
    for (int ch = 0; ch < IN_CH / BK; ch++) {
        int s = ch & 1;
        sA[s][ac4 * 4 + 0][ar] = pa0.x;
        sA[s][ac4 * 4 + 1][ar] = pa0.y;
        sA[s][ac4 * 4 + 2][ar] = pa0.z;
        sA[s][ac4 * 4 + 3][ar] = pa0.w;
        sA[s][ac4 * 4 + 0][ar + 64] = pa1.x;
        sA[s][ac4 * 4 + 1][ar + 64] = pa1.y;
        sA[s][ac4 * 4 + 2][ar + 64] = pa1.z;
        sA[s][ac4 * 4 + 3][ar + 64] = pa1.w;
        *reinterpret_cast<float4*>(&sW[s][wk][wc4 * 4]) = pw;
        __syncthreads();
        if (ch < IN_CH / BK - 1) {
            int kofs = (ch + 1) * BK;
            pa0 = __ldg(xr0 + kofs / 4);
            pa1 = __ldg(xr1 + kofs / 4);
            pw  = __ldg(reinterpret_cast<const float4*>(
                            W1 + (size_t)(kofs + wk) * HID_CH) + wc4);
        }
#pragma unroll
        for (int k = 0; k < BK; k++) {
            ulonglong2 aA = *reinterpret_cast<const ulonglong2*>(&sA[s][k][ty * 8]);
            ulonglong2 aB = *reinterpret_cast<const ulonglong2*>(&sA[s][k][ty * 8 + 4]);
            float4 wv = *reinterpret_cast<const float4*>(&sW[s][k][tx * 4]);
            unsigned long long w0 = pack2(wv.x, wv.x);
            unsigned long long w1 = pack2(wv.y, wv.y);
            unsigned long long w2 = pack2(wv.z, wv.z);
            unsigned long long w3 = pack2(wv.w, wv.w);
            acc[0][0] = fma2(aA.x, w0, acc[0][0]);
            acc[0][1] = fma2(aA.x, w1, acc[0][1]);
            acc[0][2] = fma2(aA.x, w2, acc[0][2]);
            acc[0][3] = fma2(aA.x, w3, acc[0][3]);
            acc[1][0] = fma2(aA.y, w0, acc[1][0]);
            acc[1][1] = fma2(aA.y, w1, acc[1][1]);
            acc[1][2] = fma2(aA.y, w2, acc[1][2]);
            acc[1][3] = fma2(aA.y, w3, acc[1][3]);
            acc[2][0] = fma2(aB.x, w0, acc[2][0]);
            acc[2][1] = fma2(aB.x, w1, acc[2][1]);
            acc[2][2] = fma2(aB.x, w2, acc[2][2]);
            acc[2][3] = fma2(aB.x, w3, acc[2][3]);
            acc[3][0] = fma2(aB.y, w0, acc[3][0]);
            acc[3][1] = fma2(aB.y, w1, acc[3][1]);
            acc[3][2] = fma2(aB.y, w2, acc[3][2]);
            acc[3][3] = fma2(aB.y, w3, acc[3][3]);
        }
    }
#pragma unroll
    for (int rp = 0; rp < 4; rp++) {
        int r = row0 + ty * 8 + rp * 2;
        float2 c0 = ull2f2(acc[rp][0]), c1 = ull2f2(acc[rp][1]);
        float2 c2 = ull2f2(acc[rp][2]), c3 = ull2f2(acc[rp][3]);
        if (r < N_NODES) {
            float4 lo = make_float4(c0.x, c1.x, c2.x, c3.x);
            *reinterpret_cast<float4*>(g_h1 + (size_t)r * HID_CH + tx * 4) = lo;
        }
        if (r + 1 < N_NODES) {
            float4 hi = make_float4(c0.y, c1.y, c2.y, c3.y);
            *reinterpret_cast<float4*>(g_h1 + (size_t)(r + 1) * HID_CH + tx * 4) = hi;
        }
    }
}

// ---------------- agg1: act1 = relu(A @ h1 + b1); 2 edges per warp-load ----------------
// lane = half*16 + q : half picks edge parity, q picks float4 channel group
__global__ __launch_bounds__(256) void k_agg1(const float* __restrict__ b1) {
    int t = blockIdx.x * 256 + threadIdx.x;
    int node = t >> 5;
    if (node >= N_NODES) return;
    int lane = t & 31;
    int half = lane >> 4;
    int q    = lane & 15;

    int beg = g_off[node];
    int dg  = g_off[node + 1] - beg;
    if (lane == 0) g_deg[node] = 0;      // restore zero-invariant for next call

    const float4* h1v = reinterpret_cast<const float4*>(g_h1);
    float4 a0{0,0,0,0}, a1{0,0,0,0}, a2{0,0,0,0}, a3{0,0,0,0};

    for (int base = 0; base < dg; base += 32) {
        int rem = dg - base;
        int idx = (lane < rem) ? __ldg(g_csr_src + beg + base + lane) : 0;
#pragma unroll
        for (int j = 0; j < 16; j += 4) {
            if (2 * j >= rem) break;     // warp-uniform
            int s0 = __shfl_sync(0xffffffffu, idx, 2 * j + 0 + half);
            int s1 = __shfl_sync(0xffffffffu, idx, 2 * j + 2 + half);
            int s2 = __shfl_sync(0xffffffffu, idx, 2 * j + 4 + half);
            int s3 = __shfl_sync(0xffffffffu, idx, 2 * j + 6 + half);
            if (2 * j + 0 + half < rem) {
                float4 v = __ldg(h1v + (size_t)s0 * 16 + q);
                a0.x += v.x; a0.y += v.y; a0.z += v.z; a0.w += v.w;
            }
            if (2 * j + 2 + half < rem) {
                float4 v = __ldg(h1v + (size_t)s1 * 16 + q);
                a1.x += v.x; a1.y += v.y; a1.z += v.z; a1.w += v.w;
            }
            if (2 * j + 4 + half < rem) {
                float4 v = __ldg(h1v + (size_t)s2 * 16 + q);
                a2.x += v.x; a2.y += v.y; a2.z += v.z; a2.w += v.w;
            }
            if (2 * j + 6 + half < rem) {
                float4 v = __ldg(h1v + (size_t)s3 * 16 + q);
                a3.x += v.x; a3.y += v.y; a3.z += v.z; a3.w += v.w;
            }
        }
    }
    float4 A;
    A.x = (a0.x + a1.x) + (a2.x + a3.x);
    A.y = (a0.y + a1.y) + (a2.y + a3.y);
    A.z = (a0.z + a1.z) + (a2.z + a3.z);
    A.w = (a0.w + a1.w) + (a2.w + a3.w);
    // combine the two edge-parity halves (lanes l and l^16 share channel group q)
    A.x += __shfl_xor_sync(0xffffffffu, A.x, 16);
    A.y += __shfl_xor_sync(0xffffffffu, A.y, 16);
    A.z += __shfl_xor_sync(0xffffffffu, A.z, 16);
    A.w += __shfl_xor_sync(0xffffffffu, A.w, 16);
    if (half == 0) {
        float4 b = __ldg(reinterpret_cast<const float4*>(b1) + q);
        A.x = fmaxf(A.x + b.x, 0.f);
        A.y = fmaxf(A.y + b.y, 0.f);
        A.z = fmaxf(A.z + b.z, 0.f);
        A.w = fmaxf(A.w + b.w, 0.f);
        reinterpret_cast<float4*>(g_act1)[(size_t)node * 16 + q] = A;
    }
}

// ---------------- gemm2: m2 = act1 @ W2 (64->32), double-buffered (R8-proven) ----------------
__global__ __launch_bounds__(256) void k_gemm2(const float* __restrict__ W2) {
    __shared__ __align__(16) float sA[2][BK][SA_PAD];
    __shared__ __align__(16) float sW[2][BK][CLS_CH];
    int tid = threadIdx.x;
    int tx = tid & 15;
    int ty = tid >> 4;
    int row0 = blockIdx.x * BM;
    int ar = tid >> 2, ac4 = tid & 3;
    int wk = tid >> 3, wc4 = tid & 7;
    int gr0 = min(row0 + ar,      N_NODES - 1);
    int gr1 = min(row0 + ar + 64, N_NODES - 1);

    float4 pa0, pa1, pw;
    pa0 = *reinterpret_cast<const float4*>(g_act1 + (size_t)gr0 * HID_CH + ac4 * 4);
    pa1 = *reinterpret_cast<const float4*>(g_act1 + (size_t)gr1 * HID_CH + ac4 * 4);
    if (tid < 128)
        pw = __ldg(reinterpret_cast<const float4*>(W2 + (size_t)wk * CLS_CH) + wc4);

    unsigned long long acc[4][2];
#pragma unroll
    for (int i = 0; i < 4; i++) { acc[i][0] = 0ull; acc[i][1] = 0ull; }

#pragma unroll 1
    for (int ch = 0; ch < HID_CH / BK; ch++) {
        int s = ch & 1;
        sA[s][ac4 * 4 + 0][ar] = pa0.x;
        sA[s][ac4 * 4 + 1][ar] = pa0.y;
        sA[s][ac4 * 4 + 2][ar] = pa0.z;
        sA[s][ac4 * 4 + 3][ar] = pa0.w;
        sA[s][ac4 * 4 + 0][ar + 64] = pa1.x;
        sA[s][ac4 * 4 + 1][ar + 64] = pa1.y;
        sA[s][ac4 * 4 + 2][ar + 64] = pa1.z;
        sA[s][ac4 * 4 + 3][ar + 64] = pa1.w;
        if (tid < 128)
            *reinterpret_cast<float4*>(&sW[s][wk][wc4 * 4]) = pw;
        __syncthreads();
        if (ch < HID_CH / BK - 1) {
            int kofs = (ch + 1) * BK;
            pa0 = *reinterpret_cast<const float4*>(
                g_act1 + (size_t)gr0 * HID_CH + kofs + ac4 * 4);
            pa1 = *reinterpret_cast<const float4*>(
                g_act1 + (size_t)gr1 * HID_CH + kofs + ac4 * 4);
            if (tid < 128)
                pw = __ldg(reinterpret_cast<const float4*>(
                               W2 + (size_t)(kofs + wk) * CLS_CH) + wc4);
        }
#pragma unroll
        for (int k = 0; k < BK; k++) {
            ulonglong2 aA = *reinterpret_cast<const ulonglong2*>(&sA[s][k][ty * 8]);
            ulonglong2 aB = *reinterpret_cast<const ulonglong2*>(&sA[s][k][ty * 8 + 4]);
            float2 wv = *reinterpret_cast<const float2*>(&sW[s][k][tx * 2]);
            unsigned long long w0 = pack2(wv.x, wv.x);
            unsigned long long w1 = pack2(wv.y, wv.y);
            acc[0][0] = fma2(aA.x, w0, acc[0][0]);
            acc[0][1] = fma2(aA.x, w1, acc[0][1]);
            acc[1][0] = fma2(aA.y, w0, acc[1][0]);
            acc[1][1] = fma2(aA.y, w1, acc[1][1]);
            acc[2][0] = fma2(aB.x, w0, acc[2][0]);
            acc[2][1] = fma2(aB.x, w1, acc[2][1]);
            acc[3][0] = fma2(aB.y, w0, acc[3][0]);
            acc[3][1] = fma2(aB.y, w1, acc[3][1]);
        }
    }
#pragma unroll
    for (int rp = 0; rp < 4; rp++) {
        int r = row0 + ty * 8 + rp * 2;
        float2 c0 = ull2f2(acc[rp][0]), c1 = ull2f2(acc[rp][1]);
        if (r < N_NODES) {
            float2 lo = make_float2(c0.x, c1.x);
            *reinterpret_cast<float2*>(g_m2 + (size_t)r * CLS_CH + tx * 2) = lo;
        }
        if (r + 1 < N_NODES) {
            float2 hi = make_float2(c0.y, c1.y);
            *reinterpret_cast<float2*>(g_m2 + (size_t)(r + 1) * CLS_CH + tx * 2) = hi;
        }
    }
}

// ---------------- agg2: out = sigmoid(A @ m2 + b2); 4 edges per warp-load ----------------
// lane = grp*8 + q : grp picks edge slot, q picks float4 channel group
__global__ __launch_bounds__(256) void k_agg2(const float* __restrict__ b2,
                                              float* __restrict__ out) {
    int t = blockIdx.x * 256 + threadIdx.x;
    int node = t >> 5;
    if (node >= N_NODES) return;
    int lane = t & 31;
    int grp = lane >> 3;
    int q   = lane & 7;

    int beg = g_off[node];
    int dg  = g_off[node + 1] - beg;

    const float4* m2v = reinterpret_cast<const float4*>(g_m2);
    float4 a0{0,0,0,0}, a1{0,0,0,0}, a2{0,0,0,0}, a3{0,0,0,0};

    for (int base = 0; base < dg; base += 32) {
        int rem = dg - base;
        int idx = (lane < rem) ? __ldg(g_csr_src + beg + base + lane) : 0;
#pragma unroll
        for (int j = 0; j < 8; j += 4) {
            if (4 * j >= rem) break;     // warp-uniform
            int s0 = __shfl_sync(0xffffffffu, idx, 4 * (j + 0) + grp);
            int s1 = __shfl_sync(0xffffffffu, idx, 4 * (j + 1) + grp);
            int s2 = __shfl_sync(0xffffffffu, idx, 4 * (j + 2) + grp);
            int s3 = __shfl_sync(0xffffffffu, idx, 4 * (j + 3) + grp);
            if (4 * (j + 0) + grp < rem) {
                float4 v = __ldg(m2v + (size_t)s0 * 8 + q);
                a0.x += v.x; a0.y += v.y; a0.z += v.z; a0.w += v.w;
            }
            if (4 * (j + 1) + grp < rem) {
                float4 v = __ldg(m2v + (size_t)s1 * 8 + q);
                a1.x += v.x; a1.y += v.y; a1.z += v.z; a1.w += v.w;
            }
            if (4 * (j + 2) + grp < rem) {
                float4 v = __ldg(m2v + (size_t)s2 * 8 + q);
                a2.x += v.x; a2.y += v.y; a2.z += v.z; a2.w += v.w;
            }
            if (4 * (j + 3) + grp < rem) {
                float4 v = __ldg(m2v + (size_t)s3 * 8 + q);
                a3.x += v.x; a3.y += v.y; a3.z += v.z; a3.w += v.w;
            }
        }
    }
    float4 A;
    A.x = (a0.x + a1.x) + (a2.x + a3.x);
    A.y = (a0.y + a1.y) + (a2.y + a3.y);
    A.z = (a0.z + a1.z) + (a2.z + a3.z);
    A.w = (a0.w + a1.w) + (a2.w + a3.w);
    // combine the 4 edge groups (lanes sharing q)
    A.x += __shfl_xor_sync(0xffffffffu, A.x, 8);
    A.y += __shfl_xor_sync(0xffffffffu, A.y, 8);
    A.z += __shfl_xor_sync(0xffffffffu, A.z, 8);
    A.w += __shfl_xor_sync(0xffffffffu, A.w, 8);
    A.x += __shfl_xor_sync(0xffffffffu, A.x, 16);
    A.y += __shfl_xor_sync(0xffffffffu, A.y, 16);
    A.z += __shfl_xor_sync(0xffffffffu, A.z, 16);
    A.w += __shfl_xor_sync(0xffffffffu, A.w, 16);
    if (lane < 8) {
        float4 b = __ldg(reinterpret_cast<const float4*>(b2) + q);
        A.x = 1.f / (1.f + __expf(-(A.x + b.x)));
        A.y = 1.f / (1.f + __expf(-(A.y + b.y)));
        A.z = 1.f / (1.f + __expf(-(A.z + b.z)));
        A.w = 1.f / (1.f + __expf(-(A.w + b.w)));
        reinterpret_cast<float4*>(out)[(size_t)node * 8 + q] = A;
    }
}

extern "C" void kernel_launch(void* const* d_in, const int* in_sizes, int n_in,
                              void* d_out, int out_size) {
    const float* x  = (const float*)d_in[0];
    const int*   ei = (const int*)  d_in[1];
    const float* W1 = (const float*)d_in[2];
    const float* b1 = (const float*)d_in[3];
    const float* W2 = (const float*)d_in[4];
    const float* b2 = (const float*)d_in[5];
    float* out = (float*)d_out;
    const int* src = ei;
    const int* dst = ei + N_EDGES;

    k_hist<<<(N_EDGES + 255) / 256, 256>>>(dst);
    k_scan1<<<NB, SCAN_B>>>();
    k_scan23<<<NB, SCAN_B>>>();
    k_fill<<<(N_EDGES + 255) / 256, 256>>>(src, dst);   // <- profiled (idx 3)
    k_gemm1<<<(N_NODES + BM - 1) / BM, 256>>>(x, W1);
    k_agg1<<<(N_NODES * 32 + 255) / 256, 256>>>(b1);
    k_gemm2<<<(N_NODES + BM - 1) / BM, 256>>>(W2);
    k_agg2<<<(N_NODES * 32 + 255) / 256, 256>>>(b2, out);
}